// round 9
// baseline (speedup 1.0000x reference)
#include <cuda_runtime.h>
#include <cuda_fp16.h>

#define MAX_NODES 100000
#define MAX_EDGES 3200000

// ---------------- scratch (device globals; no allocation allowed) ------------
__device__ int    g_is32;
__device__ int    g_cnt[MAX_NODES];
__device__ int    g_rowptr[MAX_NODES + 1];
__device__ int    g_cursor[MAX_NODES];
__device__ float  g_dinv[MAX_NODES];
__device__ int    g_col[MAX_EDGES];
__device__ int    g_bsum[128];
__device__ __align__(256) __half g_bufH[(size_t)MAX_NODES * 64];  // gemm out (dinv-scaled)
__device__ __align__(256) __half g_bufA[(size_t)MAX_NODES * 64];  // layer-1 act

// ---------------- dtype detection -------------------------------------------
// Reference asks int64 edge_index; JAX x64-off silently yields int32.
__global__ void detect_dtype_kernel(const unsigned long long* __restrict__ ei) {
    __shared__ int f;
    if (threadIdx.x == 0) f = 0;
    __syncthreads();
    if (threadIdx.x < 64 && (ei[threadIdx.x] >> 32)) f = 1;
    __syncthreads();
    if (threadIdx.x == 0) g_is32 = f;
}

// Count in-degree: read ONLY the dst half, 4 edges/thread vectorized.
__global__ void count_kernel(const void* __restrict__ eiv, int E, int N) {
    int i4 = (blockIdx.x * blockDim.x + threadIdx.x) * 4;
    if (i4 >= E) return;
    if (g_is32) {
        const int* dstp = (const int*)eiv + E;
        if (i4 + 4 <= E) {
            int4 v = *(const int4*)(dstp + i4);
            int a = v.x, b = v.y, c = v.z, d = v.w;
            if ((unsigned)a >= (unsigned)N) a = 0;
            if ((unsigned)b >= (unsigned)N) b = 0;
            if ((unsigned)c >= (unsigned)N) c = 0;
            if ((unsigned)d >= (unsigned)N) d = 0;
            atomicAdd(&g_cnt[a], 1);
            atomicAdd(&g_cnt[b], 1);
            atomicAdd(&g_cnt[c], 1);
            atomicAdd(&g_cnt[d], 1);
        } else {
            for (int j = i4; j < E; j++) {
                int d = dstp[j];
                if ((unsigned)d >= (unsigned)N) d = 0;
                atomicAdd(&g_cnt[d], 1);
            }
        }
    } else {
        const long long* dstp = (const long long*)eiv + E;
        int lim = (i4 + 4 <= E) ? i4 + 4 : E;
        for (int j = i4; j < lim; j++) {
            int d = (int)dstp[j];
            if ((unsigned)d >= (unsigned)N) d = 0;
            atomicAdd(&g_cnt[d], 1);
        }
    }
}

// ---------------- hierarchical exclusive scan of g_cnt ----------------------
__global__ void __launch_bounds__(1024) scan1_kernel(int N) {
    __shared__ int wsum[32];
    int t = threadIdx.x, lane = t & 31, wid = t >> 5;
    int idx = blockIdx.x * 1024 + t;
    int v = (idx < N) ? g_cnt[idx] : 0;
    int x = v;
#pragma unroll
    for (int off = 1; off < 32; off <<= 1) {
        int y = __shfl_up_sync(0xffffffffu, x, off);
        if (lane >= off) x += y;
    }
    if (lane == 31) wsum[wid] = x;
    __syncthreads();
    if (wid == 0) {
        int w = wsum[lane];
#pragma unroll
        for (int off = 1; off < 32; off <<= 1) {
            int y = __shfl_up_sync(0xffffffffu, w, off);
            if (lane >= off) w += y;
        }
        wsum[lane] = w;
    }
    __syncthreads();
    int base = (wid > 0) ? wsum[wid - 1] : 0;
    int incl = x + base;
    if (idx < N) g_rowptr[idx] = incl - v;
    if (t == 1023) g_bsum[blockIdx.x] = incl;
}

// Merged scan2+scan3: each block redundantly prefix-sums bsum[0..bid-1]
// (<=98 ints), then finalizes rowptr/cursor/dinv for its 1024 elements.
__global__ void __launch_bounds__(1024) scan23_kernel(int N, int E) {
    __shared__ int boff_s;
    int t = threadIdx.x, b = blockIdx.x;
    if (t < 32) {
        int acc = 0;
        for (int i = t; i < b; i += 32) acc += g_bsum[i];
#pragma unroll
        for (int off = 16; off > 0; off >>= 1)
            acc += __shfl_down_sync(0xffffffffu, acc, off);
        if (t == 0) boff_s = acc;
    }
    __syncthreads();
    int idx = b * 1024 + t;
    if (idx < N) {
        int excl = g_rowptr[idx] + boff_s;
        g_rowptr[idx] = excl;
        g_cursor[idx] = excl;
        g_dinv[idx]   = rsqrtf((float)(g_cnt[idx] + 1));
    }
    if (idx == 0) g_rowptr[N] = E;
}

// Fill CSR columns: read edge list directly, no intermediates.
__global__ void fill_col_kernel(const void* __restrict__ eiv, int E, int N) {
    int i = blockIdx.x * blockDim.x + threadIdx.x;
    if (i >= E) return;
    int s, d;
    if (g_is32) {
        const int* e = (const int*)eiv;
        s = e[i]; d = e[E + i];
    } else {
        const long long* e = (const long long*)eiv;
        s = (int)e[i]; d = (int)e[E + i];
    }
    if ((unsigned)s >= (unsigned)N) s = 0;
    if ((unsigned)d >= (unsigned)N) d = 0;
    int p = atomicAdd(&g_cursor[d], 1);
    g_col[p] = s;
}

// ---------------- tensor-core GEMM with inline fp32->fp16 staging ------------
// H[N,64] = fp16(dinv[row] * (X[N,K] @ W[K,64])),  X: fp32 or fp16, W: fp32.
__device__ __forceinline__ void ldsm_x4(unsigned& r0, unsigned& r1,
                                        unsigned& r2, unsigned& r3,
                                        unsigned addr) {
    asm volatile("ldmatrix.sync.aligned.m8n8.x4.shared.b16 {%0,%1,%2,%3}, [%4];"
                 : "=r"(r0), "=r"(r1), "=r"(r2), "=r"(r3) : "r"(addr));
}
__device__ __forceinline__ void ldsm_x4_t(unsigned& r0, unsigned& r1,
                                          unsigned& r2, unsigned& r3,
                                          unsigned addr) {
    asm volatile("ldmatrix.sync.aligned.m8n8.x4.trans.shared.b16 {%0,%1,%2,%3}, [%4];"
                 : "=r"(r0), "=r"(r1), "=r"(r2), "=r"(r3) : "r"(addr));
}
__device__ __forceinline__ void mma16816(float* c, unsigned a0, unsigned a1,
                                         unsigned a2, unsigned a3,
                                         unsigned b0, unsigned b1) {
    asm volatile(
        "mma.sync.aligned.m16n8k16.row.col.f32.f16.f16.f32 "
        "{%0,%1,%2,%3}, {%4,%5,%6,%7}, {%8,%9}, {%0,%1,%2,%3};"
        : "+f"(c[0]), "+f"(c[1]), "+f"(c[2]), "+f"(c[3])
        : "r"(a0), "r"(a1), "r"(a2), "r"(a3), "r"(b0), "r"(b1));
}

template <int K, typename TX>
__global__ void __launch_bounds__(128) gemm_tc_kernel(
    const TX* __restrict__ X, const float* __restrict__ W,
    __half* __restrict__ Y, int N) {
    constexpr int SA = K + 8;
    constexpr int SB = 64 + 8;
    extern __shared__ __align__(16) __half smem[];
    __half* sA = smem;               // [64][SA]
    __half* sB = smem + 64 * SA;     // [K][SB]

    int t = threadIdx.x;
    int lane = t & 31, w = t >> 5;
    int node0 = blockIdx.x * 64;

    // stage X tile (64 x K), converting fp32->fp16 if needed, zero-fill OOB
    if (sizeof(TX) == 4) {
        const float* Xf = (const float*)X;
        for (int i = t; i < 64 * (K / 4); i += 128) {
            int r = i / (K / 4), c = i % (K / 4);
            float4 v = make_float4(0.f, 0.f, 0.f, 0.f);
            if (node0 + r < N)
                v = *(const float4*)&Xf[(size_t)(node0 + r) * K + 4 * c];
            __half2 h0 = __floats2half2_rn(v.x, v.y);
            __half2 h1 = __floats2half2_rn(v.z, v.w);
            *(uint2*)&sA[r * SA + 4 * c] =
                make_uint2(*(unsigned*)&h0, *(unsigned*)&h1);
        }
    } else {
        const __half* Xh = (const __half*)X;
        for (int i = t; i < 64 * (K / 8); i += 128) {
            int r = i / (K / 8), c = i % (K / 8);
            uint4 v = make_uint4(0u, 0u, 0u, 0u);
            if (node0 + r < N)
                v = *(const uint4*)&Xh[(size_t)(node0 + r) * K + 8 * c];
            *(uint4*)&sA[r * SA + 8 * c] = v;
        }
    }
    // stage W tile (K x 64) fp32 -> fp16 (L2-resident across blocks)
    for (int i = t; i < K * 16; i += 128) {
        int r = i / 16, c = i % 16;
        float4 v = *(const float4*)&W[r * 64 + 4 * c];
        __half2 h0 = __floats2half2_rn(v.x, v.y);
        __half2 h1 = __floats2half2_rn(v.z, v.w);
        *(uint2*)&sB[r * SB + 4 * c] =
            make_uint2(*(unsigned*)&h0, *(unsigned*)&h1);
    }
    __syncthreads();

    unsigned sA_u = (unsigned)__cvta_generic_to_shared(sA);
    unsigned sB_u = (unsigned)__cvta_generic_to_shared(sB);

    float acc[8][4];
#pragma unroll
    for (int i = 0; i < 8; i++)
#pragma unroll
        for (int j = 0; j < 4; j++) acc[i][j] = 0.f;

    int mi = lane >> 3, r8 = lane & 7;
    int w16 = w * 16;

#pragma unroll
    for (int kk = 0; kk < K; kk += 16) {
        unsigned a0, a1, a2, a3;
        {
            unsigned addr = sA_u +
                ((w16 + (mi & 1) * 8 + r8) * SA + kk + (mi >> 1) * 8) * 2;
            ldsm_x4(a0, a1, a2, a3, addr);
        }
#pragma unroll
        for (int p = 0; p < 4; p++) {
            unsigned b0, b1, b2, b3;
            unsigned addr = sB_u +
                ((kk + (mi & 1) * 8 + r8) * SB + p * 16 + (mi >> 1) * 8) * 2;
            ldsm_x4_t(b0, b1, b2, b3, addr);
            mma16816(acc[2 * p],     a0, a1, a2, a3, b0, b1);
            mma16816(acc[2 * p + 1], a0, a1, a2, a3, b2, b3);
        }
    }

    // epilogue: scale rows by dinv, pack fp16, store
    int g = lane >> 2, tc = lane & 3;
    int row0 = node0 + w16 + g;
    int row1 = row0 + 8;
    float d0 = (row0 < N) ? g_dinv[row0] : 0.f;
    float d1 = (row1 < N) ? g_dinv[row1] : 0.f;
#pragma unroll
    for (int p = 0; p < 8; p++) {
        int col = p * 8 + 2 * tc;
        if (row0 < N) {
            __half2 h = __floats2half2_rn(acc[p][0] * d0, acc[p][1] * d0);
            *(__half2*)&Y[(size_t)row0 * 64 + col] = h;
        }
        if (row1 < N) {
            __half2 h = __floats2half2_rn(acc[p][2] * d1, acc[p][3] * d1);
            *(__half2*)&Y[(size_t)row1 * 64 + col] = h;
        }
    }
}

// ---------------- sparse aggregation: warp per dst node ----------------------
// H pre-scaled (h' = dinv*h). out[d] = dinv[d]*(sum h'[src] + h'[d]) + b
template <bool HALF_OUT>
__global__ void __launch_bounds__(256) agg_kernel(
    const __half* __restrict__ H, const float* __restrict__ bias,
    void* __restrict__ outv, int N) {
    int gw = (blockIdx.x * blockDim.x + threadIdx.x) >> 5;
    if (gw >= N) return;
    int lane = threadIdx.x & 31;

    int rs = g_rowptr[gw], re = g_rowptr[gw + 1];
    float ax = 0.f, ay = 0.f;

    int e = rs;
    for (; e + 8 <= re; e += 8) {
        int c[8];
#pragma unroll
        for (int i = 0; i < 8; i++) c[i] = __ldg(&g_col[e + i]);
#pragma unroll
        for (int i = 0; i < 8; i++) {
            float2 f = __half22float2(
                *(const __half2*)&H[(size_t)c[i] * 64 + 2 * lane]);
            ax += f.x;
            ay += f.y;
        }
    }
    for (; e < re; e++) {
        int c = __ldg(&g_col[e]);
        float2 f = __half22float2(*(const __half2*)&H[(size_t)c * 64 + 2 * lane]);
        ax += f.x;
        ay += f.y;
    }

    float wd = g_dinv[gw];
    float2 hs = __half22float2(*(const __half2*)&H[(size_t)gw * 64 + 2 * lane]);
    float2 bv = *(const float2*)&bias[2 * lane];
    float ox = fmaf(wd, ax + hs.x, bv.x);
    float oy = fmaf(wd, ay + hs.y, bv.y);
    if (HALF_OUT) {
        ox = fmaxf(ox, 0.f);
        oy = fmaxf(oy, 0.f);
        __half2 h = __floats2half2_rn(ox, oy);
        *(__half2*)&((__half*)outv)[(size_t)gw * 64 + 2 * lane] = h;
    } else {
        float2 o;
        o.x = ox;
        o.y = oy;
        *(float2*)&((float*)outv)[(size_t)gw * 64 + 2 * lane] = o;
    }
}

// ---------------- launch ------------------------------------------------------
extern "C" void kernel_launch(void* const* d_in, const int* in_sizes, int n_in,
                              void* d_out, int out_size) {
    const float* x   = (const float*)d_in[0];
    const void*  ei  = d_in[1];
    const float* W1  = (const float*)d_in[2];
    const float* b1  = (const float*)d_in[3];
    const float* W2  = (const float*)d_in[4];
    const float* b2  = (const float*)d_in[5];
    float*       out = (float*)d_out;

    int N = in_sizes[0] / 128;   // 100000
    int E = in_sizes[1] / 2;     // 3200000
    int nb = (N + 1023) / 1024;  // 98

    void *pH = nullptr, *pA = nullptr, *pC = nullptr;
    cudaGetSymbolAddress(&pH, g_bufH);
    cudaGetSymbolAddress(&pA, g_bufA);
    cudaGetSymbolAddress(&pC, g_cnt);
    __half* bufH = (__half*)pH;
    __half* bufA = (__half*)pA;

    int smem1 = (64 * (128 + 8) + 128 * 72) * 2;  // 35840 B
    int smem2 = (64 * (64 + 8) + 64 * 72) * 2;    // 18432 B

    static bool init = false;
    if (!init) {
        init = true;
        cudaFuncSetAttribute(gemm_tc_kernel<128, float>,
                             cudaFuncAttributeMaxDynamicSharedMemorySize, smem1);
        cudaFuncSetAttribute(gemm_tc_kernel<64, __half>,
                             cudaFuncAttributeMaxDynamicSharedMemorySize, smem2);
    }

    // --- CSR build (dst-grouped) ---
    detect_dtype_kernel<<<1, 64>>>((const unsigned long long*)ei);
    cudaMemsetAsync(pC, 0, (size_t)N * sizeof(int));
    count_kernel<<<(E / 4 + 255) / 256, 256>>>(ei, E, N);
    scan1_kernel<<<nb, 1024>>>(N);
    scan23_kernel<<<nb, 1024>>>(N, E);
    fill_col_kernel<<<(E + 255) / 256, 256>>>(ei, E, N);

    // --- layer 1: H = fp16(dinv*(x@W1)) ; a = relu(dinv_d*(sum H) + b1) ---
    gemm_tc_kernel<128, float><<<(N + 63) / 64, 128, smem1>>>(x, W1, bufH, N);
    agg_kernel<true><<<(N + 7) / 8, 256>>>(bufH, b1, bufA, N);

    // --- layer 2 ---
    gemm_tc_kernel<64, __half><<<(N + 63) / 64, 128, smem2>>>(bufA, W2, bufH, N);
    agg_kernel<false><<<(N + 7) / 8, 256>>>(bufH, b2, out, N);
}

// round 10
// speedup vs baseline: 1.3807x; 1.3807x over previous
#include <cuda_runtime.h>
#include <cuda_fp16.h>

#define MAX_NODES 100000
#define MAX_EDGES 3200000

// ---------------- scratch (device globals; no allocation allowed) ------------
__device__ int    g_is32;
__device__ int    g_cnt[MAX_NODES];
__device__ int    g_rowptr[MAX_NODES + 1];
__device__ int    g_cursor[MAX_NODES];
__device__ float  g_dinv[MAX_NODES];
__device__ int    g_col[MAX_EDGES];
__device__ int    g_bsum[128];
__device__ __align__(256) __half g_X16[(size_t)MAX_NODES * 128];  // fp16 input
__device__ __align__(256) __half g_W16[128 * 64 + 64 * 64];       // fp16 W1|W2
__device__ __align__(256) __half g_bufH[(size_t)MAX_NODES * 64];  // gemm out (dinv-scaled)
__device__ __align__(256) __half g_bufA[(size_t)MAX_NODES * 64];  // layer-1 act

// ---------------- init: zero counters + dtype detection ----------------------
// Reference asks int64 edge_index; JAX x64-off silently yields int32. True
// int64 values < 2^32 => high words all zero; int32 packing makes high half
// nonzero w.h.p. across 64 samples.
__global__ void init_kernel(const unsigned long long* __restrict__ ei, int N) {
    int i = blockIdx.x * blockDim.x + threadIdx.x;
    if (i < N) g_cnt[i] = 0;
    if (i == 0) {
        int is32 = 0;
        for (int j = 0; j < 64; j++)
            if (ei[j] >> 32) is32 = 1;
        g_is32 = is32;
    }
}

// Count in-degree: read ONLY the dst half of the edge list.
__global__ void count_kernel(const void* __restrict__ eiv, int E, int N) {
    int i = blockIdx.x * blockDim.x + threadIdx.x;
    if (i >= E) return;
    int d;
    if (g_is32) d = ((const int*)eiv)[E + i];
    else        d = (int)((const long long*)eiv)[E + i];
    if ((unsigned)d >= (unsigned)N) d = 0;
    atomicAdd(&g_cnt[d], 1);
}

// ---------------- hierarchical exclusive scan of g_cnt ----------------------
__global__ void __launch_bounds__(1024) scan1_kernel(int N) {
    __shared__ int wsum[32];
    int t = threadIdx.x, lane = t & 31, wid = t >> 5;
    int idx = blockIdx.x * 1024 + t;
    int v = (idx < N) ? g_cnt[idx] : 0;
    int x = v;
#pragma unroll
    for (int off = 1; off < 32; off <<= 1) {
        int y = __shfl_up_sync(0xffffffffu, x, off);
        if (lane >= off) x += y;
    }
    if (lane == 31) wsum[wid] = x;
    __syncthreads();
    if (wid == 0) {
        int w = wsum[lane];
#pragma unroll
        for (int off = 1; off < 32; off <<= 1) {
            int y = __shfl_up_sync(0xffffffffu, w, off);
            if (lane >= off) w += y;
        }
        wsum[lane] = w;
    }
    __syncthreads();
    int base = (wid > 0) ? wsum[wid - 1] : 0;
    int incl = x + base;
    if (idx < N) g_rowptr[idx] = incl - v;
    if (t == 1023) g_bsum[blockIdx.x] = incl;
}

// Merged scan2+scan3: each block redundantly reduces bsum[0..bid-1] (<=98
// ints), then finalizes rowptr/cursor/dinv for its 1024 elements.
__global__ void __launch_bounds__(1024) scan23_kernel(int N, int E) {
    __shared__ int boff_s;
    int t = threadIdx.x, b = blockIdx.x;
    if (t < 32) {
        int acc = 0;
        for (int i = t; i < b; i += 32) acc += g_bsum[i];
#pragma unroll
        for (int off = 16; off > 0; off >>= 1)
            acc += __shfl_down_sync(0xffffffffu, acc, off);
        if (t == 0) boff_s = acc;
    }
    __syncthreads();
    int idx = b * 1024 + t;
    if (idx < N) {
        int excl = g_rowptr[idx] + boff_s;
        g_rowptr[idx] = excl;
        g_cursor[idx] = excl;
        g_dinv[idx]   = rsqrtf((float)(g_cnt[idx] + 1));
    }
    if (idx == 0) g_rowptr[N] = E;
}

// Fill CSR columns: read edge list directly, no intermediates.
__global__ void fill_col_kernel(const void* __restrict__ eiv, int E, int N) {
    int i = blockIdx.x * blockDim.x + threadIdx.x;
    if (i >= E) return;
    int s, d;
    if (g_is32) {
        const int* e = (const int*)eiv;
        s = e[i]; d = e[E + i];
    } else {
        const long long* e = (const long long*)eiv;
        s = (int)e[i]; d = (int)e[E + i];
    }
    if ((unsigned)s >= (unsigned)N) s = 0;
    if ((unsigned)d >= (unsigned)N) d = 0;
    int p = atomicAdd(&g_cursor[d], 1);
    g_col[p] = s;
}

// ---------------- fused fp16 conversion: X + W1 + W2 -------------------------
__global__ void cvt_kernel(const float* __restrict__ X,
                           const float* __restrict__ W1,
                           const float* __restrict__ W2,
                           __half* __restrict__ Y, long long n8, int xblocks) {
    if ((int)blockIdx.x < xblocks) {
        long long i = (long long)(blockIdx.x * blockDim.x + threadIdx.x);
        if (i >= n8) return;
        float4 a = *(const float4*)&X[i * 8];
        float4 b = *(const float4*)&X[i * 8 + 4];
        __half2 h0 = __floats2half2_rn(a.x, a.y);
        __half2 h1 = __floats2half2_rn(a.z, a.w);
        __half2 h2 = __floats2half2_rn(b.x, b.y);
        __half2 h3 = __floats2half2_rn(b.z, b.w);
        uint4 pk = make_uint4(*(unsigned*)&h0, *(unsigned*)&h1,
                              *(unsigned*)&h2, *(unsigned*)&h3);
        *(uint4*)&Y[i * 8] = pk;
    } else {
        for (int i = threadIdx.x; i < 128 * 64; i += 256)
            g_W16[i] = __float2half_rn(W1[i]);
        for (int i = threadIdx.x; i < 64 * 64; i += 256)
            g_W16[128 * 64 + i] = __float2half_rn(W2[i]);
    }
}

// ---------------- tensor-core GEMM: H[N,64] = fp16(dinv * (X[N,K]@W[K,64])) --
__device__ __forceinline__ void ldsm_x4(unsigned& r0, unsigned& r1,
                                        unsigned& r2, unsigned& r3,
                                        unsigned addr) {
    asm volatile("ldmatrix.sync.aligned.m8n8.x4.shared.b16 {%0,%1,%2,%3}, [%4];"
                 : "=r"(r0), "=r"(r1), "=r"(r2), "=r"(r3) : "r"(addr));
}
__device__ __forceinline__ void ldsm_x4_t(unsigned& r0, unsigned& r1,
                                          unsigned& r2, unsigned& r3,
                                          unsigned addr) {
    asm volatile("ldmatrix.sync.aligned.m8n8.x4.trans.shared.b16 {%0,%1,%2,%3}, [%4];"
                 : "=r"(r0), "=r"(r1), "=r"(r2), "=r"(r3) : "r"(addr));
}
__device__ __forceinline__ void mma16816(float* c, unsigned a0, unsigned a1,
                                         unsigned a2, unsigned a3,
                                         unsigned b0, unsigned b1) {
    asm volatile(
        "mma.sync.aligned.m16n8k16.row.col.f32.f16.f16.f32 "
        "{%0,%1,%2,%3}, {%4,%5,%6,%7}, {%8,%9}, {%0,%1,%2,%3};"
        : "+f"(c[0]), "+f"(c[1]), "+f"(c[2]), "+f"(c[3])
        : "r"(a0), "r"(a1), "r"(a2), "r"(a3), "r"(b0), "r"(b1));
}

template <int K>
__global__ void __launch_bounds__(128) gemm_tc_kernel(
    const __half* __restrict__ X, const __half* __restrict__ W,
    __half* __restrict__ Y, int N) {
    constexpr int SA = K + 8;
    constexpr int SB = 64 + 8;
    extern __shared__ __align__(16) __half smem[];
    __half* sA = smem;               // [64][SA]
    __half* sB = smem + 64 * SA;     // [K][SB]

    int t = threadIdx.x;
    int lane = t & 31, w = t >> 5;
    int node0 = blockIdx.x * 64;

    for (int i = t; i < 64 * (K / 8); i += 128) {
        int r = i / (K / 8), c = i % (K / 8);
        uint4 v = make_uint4(0u, 0u, 0u, 0u);
        if (node0 + r < N)
            v = *(const uint4*)&X[(size_t)(node0 + r) * K + 8 * c];
        *(uint4*)&sA[r * SA + 8 * c] = v;
    }
    for (int i = t; i < K * 8; i += 128) {
        int r = i / 8, c = i % 8;
        *(uint4*)&sB[r * SB + 8 * c] = *(const uint4*)&W[r * 64 + 8 * c];
    }
    __syncthreads();

    unsigned sA_u = (unsigned)__cvta_generic_to_shared(sA);
    unsigned sB_u = (unsigned)__cvta_generic_to_shared(sB);

    float acc[8][4];
#pragma unroll
    for (int i = 0; i < 8; i++)
#pragma unroll
        for (int j = 0; j < 4; j++) acc[i][j] = 0.f;

    int mi = lane >> 3, r8 = lane & 7;
    int w16 = w * 16;

#pragma unroll
    for (int kk = 0; kk < K; kk += 16) {
        unsigned a0, a1, a2, a3;
        {
            unsigned addr = sA_u +
                ((w16 + (mi & 1) * 8 + r8) * SA + kk + (mi >> 1) * 8) * 2;
            ldsm_x4(a0, a1, a2, a3, addr);
        }
#pragma unroll
        for (int p = 0; p < 4; p++) {
            unsigned b0, b1, b2, b3;
            unsigned addr = sB_u +
                ((kk + (mi & 1) * 8 + r8) * SB + p * 16 + (mi >> 1) * 8) * 2;
            ldsm_x4_t(b0, b1, b2, b3, addr);
            mma16816(acc[2 * p],     a0, a1, a2, a3, b0, b1);
            mma16816(acc[2 * p + 1], a0, a1, a2, a3, b2, b3);
        }
    }

    int g = lane >> 2, tc = lane & 3;
    int row0 = node0 + w16 + g;
    int row1 = row0 + 8;
    float d0 = (row0 < N) ? g_dinv[row0] : 0.f;
    float d1 = (row1 < N) ? g_dinv[row1] : 0.f;
#pragma unroll
    for (int p = 0; p < 8; p++) {
        int col = p * 8 + 2 * tc;
        if (row0 < N) {
            __half2 h = __floats2half2_rn(acc[p][0] * d0, acc[p][1] * d0);
            *(__half2*)&Y[(size_t)row0 * 64 + col] = h;
        }
        if (row1 < N) {
            __half2 h = __floats2half2_rn(acc[p][2] * d1, acc[p][3] * d1);
            *(__half2*)&Y[(size_t)row1 * 64 + col] = h;
        }
    }
}

// ---------------- sparse aggregation: warp per dst node ----------------------
// H pre-scaled (h' = dinv*h). out[d] = dinv[d]*(sum h'[src] + h'[d]) + b
template <bool HALF_OUT>
__global__ void __launch_bounds__(256) agg_kernel(
    const __half* __restrict__ H, const float* __restrict__ bias,
    void* __restrict__ outv, int N) {
    int gw = (blockIdx.x * blockDim.x + threadIdx.x) >> 5;
    if (gw >= N) return;
    int lane = threadIdx.x & 31;

    int rs = g_rowptr[gw], re = g_rowptr[gw + 1];
    float ax = 0.f, ay = 0.f;

    int e = rs;
    // 16-deep index prefetch -> 16 outstanding gathers per lane
    for (; e + 16 <= re; e += 16) {
        int c[16];
#pragma unroll
        for (int i = 0; i < 16; i++) c[i] = __ldg(&g_col[e + i]);
#pragma unroll
        for (int i = 0; i < 16; i++) {
            float2 f = __half22float2(
                *(const __half2*)&H[(size_t)c[i] * 64 + 2 * lane]);
            ax += f.x;
            ay += f.y;
        }
    }
    for (; e + 8 <= re; e += 8) {
        int c[8];
#pragma unroll
        for (int i = 0; i < 8; i++) c[i] = __ldg(&g_col[e + i]);
#pragma unroll
        for (int i = 0; i < 8; i++) {
            float2 f = __half22float2(
                *(const __half2*)&H[(size_t)c[i] * 64 + 2 * lane]);
            ax += f.x;
            ay += f.y;
        }
    }
    for (; e < re; e++) {
        int c = __ldg(&g_col[e]);
        float2 f = __half22float2(*(const __half2*)&H[(size_t)c * 64 + 2 * lane]);
        ax += f.x;
        ay += f.y;
    }

    float wd = g_dinv[gw];
    float2 hs = __half22float2(*(const __half2*)&H[(size_t)gw * 64 + 2 * lane]);
    float2 bv = *(const float2*)&bias[2 * lane];
    float ox = fmaf(wd, ax + hs.x, bv.x);
    float oy = fmaf(wd, ay + hs.y, bv.y);
    if (HALF_OUT) {
        ox = fmaxf(ox, 0.f);
        oy = fmaxf(oy, 0.f);
        __half2 h = __floats2half2_rn(ox, oy);
        *(__half2*)&((__half*)outv)[(size_t)gw * 64 + 2 * lane] = h;
    } else {
        float2 o;
        o.x = ox;
        o.y = oy;
        *(float2*)&((float*)outv)[(size_t)gw * 64 + 2 * lane] = o;
    }
}

// ---------------- launch ------------------------------------------------------
extern "C" void kernel_launch(void* const* d_in, const int* in_sizes, int n_in,
                              void* d_out, int out_size) {
    const float* x   = (const float*)d_in[0];
    const void*  ei  = d_in[1];
    const float* W1  = (const float*)d_in[2];
    const float* b1  = (const float*)d_in[3];
    const float* W2  = (const float*)d_in[4];
    const float* b2  = (const float*)d_in[5];
    float*       out = (float*)d_out;

    int N = in_sizes[0] / 128;   // 100000
    int E = in_sizes[1] / 2;     // 3200000
    int nb = (N + 1023) / 1024;  // 98

    void *pX = nullptr, *pW = nullptr, *pH = nullptr, *pA = nullptr;
    cudaGetSymbolAddress(&pX, g_X16);
    cudaGetSymbolAddress(&pW, g_W16);
    cudaGetSymbolAddress(&pH, g_bufH);
    cudaGetSymbolAddress(&pA, g_bufA);
    __half* X16  = (__half*)pX;
    __half* W16  = (__half*)pW;
    __half* bufH = (__half*)pH;
    __half* bufA = (__half*)pA;

    int smem1 = (64 * (128 + 8) + 128 * 72) * 2;  // 35840 B
    int smem2 = (64 * (64 + 8) + 64 * 72) * 2;    // 18432 B
    cudaFuncSetAttribute(gemm_tc_kernel<128>,
                         cudaFuncAttributeMaxDynamicSharedMemorySize, smem1);
    cudaFuncSetAttribute(gemm_tc_kernel<64>,
                         cudaFuncAttributeMaxDynamicSharedMemorySize, smem2);

    // --- CSR build (dst-grouped) + fp16 conversion ---
    init_kernel<<<(N + 255) / 256, 256>>>((const unsigned long long*)ei, N);
    count_kernel<<<(E + 255) / 256, 256>>>(ei, E, N);
    scan1_kernel<<<nb, 1024>>>(N);
    scan23_kernel<<<nb, 1024>>>(N, E);
    fill_col_kernel<<<(E + 255) / 256, 256>>>(ei, E, N);

    long long n8 = (long long)N * 128 / 8;
    int xblocks = (int)((n8 + 255) / 256);
    cvt_kernel<<<xblocks + 1, 256>>>(x, W1, W2, X16, n8, xblocks);

    // --- layer 1: H = fp16(dinv*(x@W1)) ; a = relu(dinv_d*(sum H) + b1) ---
    gemm_tc_kernel<128><<<(N + 63) / 64, 128, smem1>>>(X16, W16, bufH, N);
    agg_kernel<true><<<(N + 7) / 8, 256>>>(bufH, b1, bufA, N);

    // --- layer 2 ---
    gemm_tc_kernel<64><<<(N + 63) / 64, 128, smem2>>>(bufA, W16 + 128 * 64, bufH, N);
    agg_kernel<false><<<(N + 7) / 8, 256>>>(bufH, b2, out, N);
}

// round 11
// speedup vs baseline: 1.4680x; 1.0632x over previous
#include <cuda_runtime.h>
#include <cuda_fp16.h>

#define MAX_NODES 100000
#define MAX_EDGES 3200000

// ---------------- scratch (device globals; no allocation allowed) ------------
// g_cnt starts zeroed (loader) and is re-zeroed by agg1 each run.
__device__ int    g_is32;
__device__ int    g_cnt[MAX_NODES];
__device__ int    g_rowptr[MAX_NODES + 1];
__device__ int    g_cursor[MAX_NODES];
__device__ float  g_dinv[MAX_NODES];
__device__ int    g_col[MAX_EDGES];
__device__ int    g_bsum[128];
__device__ __align__(256) __half g_W16[128 * 64 + 64 * 64];       // fp16 W1|W2
__device__ __align__(256) __half g_bufH[(size_t)MAX_NODES * 64];  // gemm out (dinv-scaled)
__device__ __align__(256) __half g_bufA[(size_t)MAX_NODES * 64];  // layer-1 act

// ---------------- init: dtype detection + W1/W2 fp16 conversion --------------
// Reference asks int64 edge_index; JAX x64-off silently yields int32. True
// int64 values < 2^32 => high words all zero; int32 packing makes high half
// nonzero w.h.p. across 64 samples.
__global__ void init_kernel(const unsigned long long* __restrict__ ei,
                            const float* __restrict__ W1,
                            const float* __restrict__ W2) {
    if (blockIdx.x == 0) {
        __shared__ int f;
        if (threadIdx.x == 0) f = 0;
        __syncthreads();
        if (threadIdx.x < 64 && (ei[threadIdx.x] >> 32)) f = 1;
        __syncthreads();
        if (threadIdx.x == 0) g_is32 = f;
    } else {
        int i = (blockIdx.x - 1) * 256 + threadIdx.x;
        for (; i < 128 * 64 + 64 * 64; i += 4 * 256) {
            float v = (i < 128 * 64) ? W1[i] : W2[i - 128 * 64];
            g_W16[i] = __float2half_rn(v);
        }
    }
}

// Count in-degree: read ONLY the dst half of the edge list.
__global__ void count_kernel(const void* __restrict__ eiv, int E, int N) {
    int i = blockIdx.x * blockDim.x + threadIdx.x;
    if (i >= E) return;
    int d;
    if (g_is32) d = ((const int*)eiv)[E + i];
    else        d = (int)((const long long*)eiv)[E + i];
    if ((unsigned)d >= (unsigned)N) d = 0;
    atomicAdd(&g_cnt[d], 1);
}

// ---------------- hierarchical exclusive scan of g_cnt ----------------------
__global__ void __launch_bounds__(1024) scan1_kernel(int N) {
    __shared__ int wsum[32];
    int t = threadIdx.x, lane = t & 31, wid = t >> 5;
    int idx = blockIdx.x * 1024 + t;
    int v = (idx < N) ? g_cnt[idx] : 0;
    int x = v;
#pragma unroll
    for (int off = 1; off < 32; off <<= 1) {
        int y = __shfl_up_sync(0xffffffffu, x, off);
        if (lane >= off) x += y;
    }
    if (lane == 31) wsum[wid] = x;
    __syncthreads();
    if (wid == 0) {
        int w = wsum[lane];
#pragma unroll
        for (int off = 1; off < 32; off <<= 1) {
            int y = __shfl_up_sync(0xffffffffu, w, off);
            if (lane >= off) w += y;
        }
        wsum[lane] = w;
    }
    __syncthreads();
    int base = (wid > 0) ? wsum[wid - 1] : 0;
    int incl = x + base;
    if (idx < N) g_rowptr[idx] = incl - v;
    if (t == 1023) g_bsum[blockIdx.x] = incl;
}

// Merged scan2+scan3: each block redundantly reduces bsum[0..bid-1] (<=98
// ints), then finalizes rowptr/cursor/dinv for its 1024 elements.
__global__ void __launch_bounds__(1024) scan23_kernel(int N, int E) {
    __shared__ int boff_s;
    int t = threadIdx.x, b = blockIdx.x;
    if (t < 32) {
        int acc = 0;
        for (int i = t; i < b; i += 32) acc += g_bsum[i];
#pragma unroll
        for (int off = 16; off > 0; off >>= 1)
            acc += __shfl_down_sync(0xffffffffu, acc, off);
        if (t == 0) boff_s = acc;
    }
    __syncthreads();
    int idx = b * 1024 + t;
    if (idx < N) {
        int excl = g_rowptr[idx] + boff_s;
        g_rowptr[idx] = excl;
        g_cursor[idx] = excl;
        g_dinv[idx]   = rsqrtf((float)(g_cnt[idx] + 1));
    }
    if (idx == 0) g_rowptr[N] = E;
}

// Fill CSR columns: read edge list directly, no intermediates.
__global__ void fill_col_kernel(const void* __restrict__ eiv, int E, int N) {
    int i = blockIdx.x * blockDim.x + threadIdx.x;
    if (i >= E) return;
    int s, d;
    if (g_is32) {
        const int* e = (const int*)eiv;
        s = e[i]; d = e[E + i];
    } else {
        const long long* e = (const long long*)eiv;
        s = (int)e[i]; d = (int)e[E + i];
    }
    if ((unsigned)s >= (unsigned)N) s = 0;
    if ((unsigned)d >= (unsigned)N) d = 0;
    int p = atomicAdd(&g_cursor[d], 1);
    g_col[p] = s;
}

// ---------------- tensor-core GEMM: H[N,64] = fp16(dinv * (X[N,K]@W[K,64])) --
// X: fp32 (layer 1, converted inline during smem staging) or fp16 (layer 2).
__device__ __forceinline__ void ldsm_x4(unsigned& r0, unsigned& r1,
                                        unsigned& r2, unsigned& r3,
                                        unsigned addr) {
    asm volatile("ldmatrix.sync.aligned.m8n8.x4.shared.b16 {%0,%1,%2,%3}, [%4];"
                 : "=r"(r0), "=r"(r1), "=r"(r2), "=r"(r3) : "r"(addr));
}
__device__ __forceinline__ void ldsm_x4_t(unsigned& r0, unsigned& r1,
                                          unsigned& r2, unsigned& r3,
                                          unsigned addr) {
    asm volatile("ldmatrix.sync.aligned.m8n8.x4.trans.shared.b16 {%0,%1,%2,%3}, [%4];"
                 : "=r"(r0), "=r"(r1), "=r"(r2), "=r"(r3) : "r"(addr));
}
__device__ __forceinline__ void mma16816(float* c, unsigned a0, unsigned a1,
                                         unsigned a2, unsigned a3,
                                         unsigned b0, unsigned b1) {
    asm volatile(
        "mma.sync.aligned.m16n8k16.row.col.f32.f16.f16.f32 "
        "{%0,%1,%2,%3}, {%4,%5,%6,%7}, {%8,%9}, {%0,%1,%2,%3};"
        : "+f"(c[0]), "+f"(c[1]), "+f"(c[2]), "+f"(c[3])
        : "r"(a0), "r"(a1), "r"(a2), "r"(a3), "r"(b0), "r"(b1));
}

template <int K, typename TX>
__global__ void __launch_bounds__(128) gemm_tc_kernel(
    const TX* __restrict__ X, const __half* __restrict__ W,
    __half* __restrict__ Y, int N) {
    constexpr int SA = K + 8;
    constexpr int SB = 64 + 8;
    extern __shared__ __align__(16) __half smem[];
    __half* sA = smem;               // [64][SA]
    __half* sB = smem + 64 * SA;     // [K][SB]

    int t = threadIdx.x;
    int lane = t & 31, w = t >> 5;
    int node0 = blockIdx.x * 64;

    // stage X tile (64 x K): fp32 path converts inline, fp16 path copies
    if (sizeof(TX) == 4) {
        const float* Xf = (const float*)X;
        for (int i = t; i < 64 * (K / 8); i += 128) {
            int r = i / (K / 8), c = i % (K / 8);
            float4 a = make_float4(0.f, 0.f, 0.f, 0.f);
            float4 b = make_float4(0.f, 0.f, 0.f, 0.f);
            if (node0 + r < N) {
                a = *(const float4*)&Xf[(size_t)(node0 + r) * K + 8 * c];
                b = *(const float4*)&Xf[(size_t)(node0 + r) * K + 8 * c + 4];
            }
            __half2 h0 = __floats2half2_rn(a.x, a.y);
            __half2 h1 = __floats2half2_rn(a.z, a.w);
            __half2 h2 = __floats2half2_rn(b.x, b.y);
            __half2 h3 = __floats2half2_rn(b.z, b.w);
            *(uint4*)&sA[r * SA + 8 * c] =
                make_uint4(*(unsigned*)&h0, *(unsigned*)&h1,
                           *(unsigned*)&h2, *(unsigned*)&h3);
        }
    } else {
        const __half* Xh = (const __half*)X;
        for (int i = t; i < 64 * (K / 8); i += 128) {
            int r = i / (K / 8), c = i % (K / 8);
            uint4 v = make_uint4(0u, 0u, 0u, 0u);
            if (node0 + r < N)
                v = *(const uint4*)&Xh[(size_t)(node0 + r) * K + 8 * c];
            *(uint4*)&sA[r * SA + 8 * c] = v;
        }
    }
    // stage W tile (K x 64), already fp16
    for (int i = t; i < K * 8; i += 128) {
        int r = i / 8, c = i % 8;
        *(uint4*)&sB[r * SB + 8 * c] = *(const uint4*)&W[r * 64 + 8 * c];
    }
    __syncthreads();

    unsigned sA_u = (unsigned)__cvta_generic_to_shared(sA);
    unsigned sB_u = (unsigned)__cvta_generic_to_shared(sB);

    float acc[8][4];
#pragma unroll
    for (int i = 0; i < 8; i++)
#pragma unroll
        for (int j = 0; j < 4; j++) acc[i][j] = 0.f;

    int mi = lane >> 3, r8 = lane & 7;
    int w16 = w * 16;

#pragma unroll
    for (int kk = 0; kk < K; kk += 16) {
        unsigned a0, a1, a2, a3;
        {
            unsigned addr = sA_u +
                ((w16 + (mi & 1) * 8 + r8) * SA + kk + (mi >> 1) * 8) * 2;
            ldsm_x4(a0, a1, a2, a3, addr);
        }
#pragma unroll
        for (int p = 0; p < 4; p++) {
            unsigned b0, b1, b2, b3;
            unsigned addr = sB_u +
                ((kk + (mi & 1) * 8 + r8) * SB + p * 16 + (mi >> 1) * 8) * 2;
            ldsm_x4_t(b0, b1, b2, b3, addr);
            mma16816(acc[2 * p],     a0, a1, a2, a3, b0, b1);
            mma16816(acc[2 * p + 1], a0, a1, a2, a3, b2, b3);
        }
    }

    // epilogue: scale rows by dinv, pack fp16, store
    int g = lane >> 2, tc = lane & 3;
    int row0 = node0 + w16 + g;
    int row1 = row0 + 8;
    float d0 = (row0 < N) ? g_dinv[row0] : 0.f;
    float d1 = (row1 < N) ? g_dinv[row1] : 0.f;
#pragma unroll
    for (int p = 0; p < 8; p++) {
        int col = p * 8 + 2 * tc;
        if (row0 < N) {
            __half2 h = __floats2half2_rn(acc[p][0] * d0, acc[p][1] * d0);
            *(__half2*)&Y[(size_t)row0 * 64 + col] = h;
        }
        if (row1 < N) {
            __half2 h = __floats2half2_rn(acc[p][2] * d1, acc[p][3] * d1);
            *(__half2*)&Y[(size_t)row1 * 64 + col] = h;
        }
    }
}

// ---------------- sparse aggregation: warp per dst node ----------------------
// H pre-scaled (h' = dinv*h). out[d] = dinv[d]*(sum h'[src] + h'[d]) + b
// HALF_OUT (layer 1) additionally re-zeros g_cnt for the next graph replay.
template <bool HALF_OUT>
__global__ void __launch_bounds__(256) agg_kernel(
    const __half* __restrict__ H, const float* __restrict__ bias,
    void* __restrict__ outv, int N) {
    int gw = (blockIdx.x * blockDim.x + threadIdx.x) >> 5;
    if (gw >= N) return;
    int lane = threadIdx.x & 31;

    if (HALF_OUT && lane == 0) g_cnt[gw] = 0;  // restore invariant for next run

    int rs = g_rowptr[gw], re = g_rowptr[gw + 1];
    float ax = 0.f, ay = 0.f;

    int e = rs;
    for (; e + 16 <= re; e += 16) {
        int c[16];
#pragma unroll
        for (int i = 0; i < 16; i++) c[i] = __ldg(&g_col[e + i]);
#pragma unroll
        for (int i = 0; i < 16; i++) {
            float2 f = __half22float2(
                *(const __half2*)&H[(size_t)c[i] * 64 + 2 * lane]);
            ax += f.x;
            ay += f.y;
        }
    }
    for (; e + 8 <= re; e += 8) {
        int c[8];
#pragma unroll
        for (int i = 0; i < 8; i++) c[i] = __ldg(&g_col[e + i]);
#pragma unroll
        for (int i = 0; i < 8; i++) {
            float2 f = __half22float2(
                *(const __half2*)&H[(size_t)c[i] * 64 + 2 * lane]);
            ax += f.x;
            ay += f.y;
        }
    }
    for (; e < re; e++) {
        int c = __ldg(&g_col[e]);
        float2 f = __half22float2(*(const __half2*)&H[(size_t)c * 64 + 2 * lane]);
        ax += f.x;
        ay += f.y;
    }

    float wd = g_dinv[gw];
    float2 hs = __half22float2(*(const __half2*)&H[(size_t)gw * 64 + 2 * lane]);
    float2 bv = *(const float2*)&bias[2 * lane];
    float ox = fmaf(wd, ax + hs.x, bv.x);
    float oy = fmaf(wd, ay + hs.y, bv.y);
    if (HALF_OUT) {
        ox = fmaxf(ox, 0.f);
        oy = fmaxf(oy, 0.f);
        __half2 h = __floats2half2_rn(ox, oy);
        *(__half2*)&((__half*)outv)[(size_t)gw * 64 + 2 * lane] = h;
    } else {
        float2 o;
        o.x = ox;
        o.y = oy;
        *(float2*)&((float*)outv)[(size_t)gw * 64 + 2 * lane] = o;
    }
}

// ---------------- launch ------------------------------------------------------
extern "C" void kernel_launch(void* const* d_in, const int* in_sizes, int n_in,
                              void* d_out, int out_size) {
    const float* x   = (const float*)d_in[0];
    const void*  ei  = d_in[1];
    const float* W1  = (const float*)d_in[2];
    const float* b1  = (const float*)d_in[3];
    const float* W2  = (const float*)d_in[4];
    const float* b2  = (const float*)d_in[5];
    float*       out = (float*)d_out;

    int N = in_sizes[0] / 128;   // 100000
    int E = in_sizes[1] / 2;     // 3200000
    int nb = (N + 1023) / 1024;  // 98

    void *pW = nullptr, *pH = nullptr, *pA = nullptr;
    cudaGetSymbolAddress(&pW, g_W16);
    cudaGetSymbolAddress(&pH, g_bufH);
    cudaGetSymbolAddress(&pA, g_bufA);
    __half* W16  = (__half*)pW;
    __half* bufH = (__half*)pH;
    __half* bufA = (__half*)pA;

    int smem1 = (64 * (128 + 8) + 128 * 72) * 2;  // 35840 B
    int smem2 = (64 * (64 + 8) + 64 * 72) * 2;    // 18432 B
    static bool init = false;
    if (!init) {
        init = true;
        cudaFuncSetAttribute(gemm_tc_kernel<128, float>,
                             cudaFuncAttributeMaxDynamicSharedMemorySize, smem1);
        cudaFuncSetAttribute(gemm_tc_kernel<64, __half>,
                             cudaFuncAttributeMaxDynamicSharedMemorySize, smem2);
    }

    // --- CSR build (dst-grouped); g_cnt arrives zeroed (loader / prev agg1) ---
    init_kernel<<<5, 256>>>((const unsigned long long*)ei, W1, W2);
    count_kernel<<<(E + 255) / 256, 256>>>(ei, E, N);
    scan1_kernel<<<nb, 1024>>>(N);
    scan23_kernel<<<nb, 1024>>>(N, E);
    fill_col_kernel<<<(E + 255) / 256, 256>>>(ei, E, N);

    // --- layer 1: H = fp16(dinv*(x@W1)) ; a = relu(dinv_d*(sum H) + b1) ---
    gemm_tc_kernel<128, float><<<(N + 63) / 64, 128, smem1>>>(x, W16, bufH, N);
    agg_kernel<true><<<(N + 7) / 8, 256>>>(bufH, b1, bufA, N);

    // --- layer 2 ---
    gemm_tc_kernel<64, __half><<<(N + 63) / 64, 128, smem2>>>(
        bufA, W16 + 128 * 64, bufH, N);
    agg_kernel<false><<<(N + 7) / 8, 256>>>(bufH, b2, out, N);
}